// round 8
// baseline (speedup 1.0000x reference)
#include <cuda_runtime.h>
#include <cstdint>

// EncodeLayer: SSD anchor matching + box encoding.
// labels:        [B=64, M=100, 5]  (x1,y1,x2,y2,cls), cls==0 => padding row
// default_boxes: [N=8732, 4]
// out: labeled [B, N, 5] (2,794,240 f32) then ious [B, 101, N] (56,443,648 f32)

#define BATCH   64
#define MROWS   100
#define NGT     101          // MROWS + prepended zero row
#define NANCH   8732
#define TPB     128
#define APT     4            // anchors per thread
#define APB     (TPB * APT)  // 512 anchors per block
#define NBLKX   ((NANCH + APB - 1) / APB)   // 18 (last block: 28 anchors)

// Hot-loop division: rcp.approx (~1-2 ulp) + FMUL. Exact for n==0.
__device__ __forceinline__ float approx_div(float n, float d) {
    float r;
    asm("rcp.approx.f32 %0, %1;" : "=f"(r) : "f"(d));
    return n * r;
}

// Epilogue division: one quotient refinement on top (~0.5-1 ulp), branch-free.
__device__ __forceinline__ float fast_div(float n, float d) {
    float r;
    asm("rcp.approx.f32 %0, %1;" : "=f"(r) : "f"(d));
    float q0  = n * r;
    float rem = __fmaf_rn(-d, q0, n);
    return __fmaf_rn(rem, r, q0);
}

// 1D bulk copy SMEM -> GMEM (async proxy; issue-once, off the per-lane LSU path).
__device__ __forceinline__ void bulk_s2g(void* gptr, uint32_t saddr, uint32_t bytes) {
    asm volatile("cp.async.bulk.global.shared::cta.bulk_group [%0], [%1], %2;"
                 :: "l"(gptr), "r"(saddr), "r"(bytes) : "memory");
}
__device__ __forceinline__ void bulk_commit() {
    asm volatile("cp.async.bulk.commit_group;" ::: "memory");
}
template <int N>
__device__ __forceinline__ void bulk_wait() {
    asm volatile("cp.async.bulk.wait_group %0;" :: "n"(N) : "memory");
}
__device__ __forceinline__ void fence_proxy_async_shared() {
    asm volatile("fence.proxy.async.shared::cta;" ::: "memory");
}
__device__ __forceinline__ uint32_t smem_u32(const void* p) {
    return (uint32_t)__cvta_generic_to_shared(p);
}

__global__ __launch_bounds__(TPB)
void encode_layer_kernel(const float* __restrict__ labels,
                         const float* __restrict__ dboxes,
                         float* __restrict__ out_labeled,   // [B, N, 5]
                         float* __restrict__ out_ious)      // [B, 101, N]
{
    __shared__ float4 sbox[NGT];   // gt box (zeroed if cls==0, row 0 = zero row)
    __shared__ float  sarea[NGT];  // gt area (0 for invalid rows)
    __shared__ float  scls[NGT];   // original class value
    __shared__ __align__(16) float stage[2][4][APB];   // double-buffered 4-row iou stage (16KB)

    const int b   = blockIdx.y;
    const int tid = threadIdx.x;

    // ---- stage GT table for this batch into smem ----
    for (int r = tid; r < NGT; r += TPB) {
        float x1 = 0.f, y1 = 0.f, x2 = 0.f, y2 = 0.f, c = 0.f;
        if (r > 0) {
            const float* L = labels + ((size_t)b * MROWS + (r - 1)) * 5;
            x1 = L[0]; y1 = L[1]; x2 = L[2]; y2 = L[3]; c = L[4];
            if (c == 0.0f) { x1 = 0.f; y1 = 0.f; x2 = 0.f; y2 = 0.f; }
        }
        sbox[r]  = make_float4(x1, y1, x2, y2);
        sarea[r] = (x2 - x1) * (y2 - y1);
        scls[r]  = c;
    }
    __syncthreads();

    const int blk_n0 = blockIdx.x * APB;
    const int n0     = blk_n0 + tid * APT;
    const int valid  = min(APB, NANCH - blk_n0);     // anchors this block really owns
    const uint32_t cp_bytes = (uint32_t)valid * 4u;  // 2048 for full blocks, 112 for tail

    // ---- per-thread anchor registers (clamped loads for tail threads; their
    //      stage slots are garbage but never copied: cp_bytes excludes them) ----
    float ax1[APT], ay1[APT], ax2[APT], ay2[APT], aarea[APT];
#pragma unroll
    for (int i = 0; i < APT; i++) {
        int ai = n0 + i;
        if (ai >= NANCH) ai = NANCH - 1;
        const float4 db = *reinterpret_cast<const float4*>(dboxes + (size_t)ai * 4);
        ax1[i] = db.x; ay1[i] = db.y; ax2[i] = db.z; ay2[i] = db.w;
        aarea[i] = (db.z - db.x) * (db.w - db.y);
    }

    // argmax state: row 0 (zero row, iou==0) is the default winner; strict >
    // against best=0 reproduces jnp.argmax first-occurrence semantics.
    float best[APT] = {0.f, 0.f, 0.f, 0.f};
    int   bidx[APT] = {0, 0, 0, 0};

    char* gbase = (char*)(out_ious + (size_t)b * NGT * NANCH + blk_n0);
    const uint32_t s_stage = smem_u32(&stage[0][0][0]);
    const uint32_t my_off  = (uint32_t)tid * APT * 4u;   // byte offset within a row

    // ---- prologue: m=0 zero row via stage[0][0] ----
    *reinterpret_cast<float4*>(&stage[0][0][tid * APT]) = make_float4(0.f, 0.f, 0.f, 0.f);
    __syncthreads();
    if (tid == 0) {
        fence_proxy_async_shared();
        bulk_s2g(gbase, s_stage, cp_bytes);
        bulk_commit();
    }
    __syncthreads();

    // ---- 25 groups of 4 GT rows; group g fills buffer p=1-(g&1) ----
    for (int g = 0; g < 25; g++) {
        const int p = 1 - (g & 1);
        const int m0 = 1 + 4 * g;
#pragma unroll
        for (int mm = 0; mm < 4; mm++) {
            const int m = m0 + mm;
            const float4 tb = sbox[m];
            const float  ta = sarea[m];
            float4 o;
            float* op = &o.x;
#pragma unroll
            for (int i = 0; i < APT; i++) {
                float ix1 = fmaxf(tb.x, ax1[i]);
                float iy1 = fmaxf(tb.y, ay1[i]);
                float ix2 = fminf(tb.z, ax2[i]);
                float iy2 = fminf(tb.w, ay2[i]);
                // w,h < 1 always, so saturate == max(.,0); fuses into FADD.SAT.
                float w = __saturatef(ix2 - ix1);
                float h = __saturatef(iy2 - iy1);
                float inter = w * h;
                float denom = (ta + aarea[i]) - inter;
                float iou = approx_div(inter, denom);
                op[i] = iou;
                if (iou > best[i]) { best[i] = iou; bidx[i] = m; }  // first-occurrence argmax
            }
            *reinterpret_cast<float4*>(&stage[p][mm][tid * APT]) = o;
        }
        __syncthreads();                       // all STS for this buffer visible
        if (tid == 0) {
            fence_proxy_async_shared();
            const uint32_t sbuf = s_stage + (uint32_t)p * 4 * APB * 4;
#pragma unroll
            for (int mm = 0; mm < 4; mm++)
                bulk_s2g(gbase + (size_t)(m0 + mm) * NANCH * 4,
                         sbuf + (uint32_t)mm * APB * 4, cp_bytes);
            bulk_commit();
            bulk_wait<1>();                    // previous buffer's group retired
        }
        __syncthreads();                       // safe to refill the other buffer
    }

    // ---- epilogue: gather winner, encode offsets (tiny; plain STG) ----
    if (n0 < NANCH) {
        float outbuf[APT * 5];
#pragma unroll
        for (int i = 0; i < APT; i++) {
            const bool pos = best[i] > 0.5f;
            const int  idx = pos ? bidx[i] : 0;
            const float4 gb = sbox[idx];
            const float  c  = scls[idx];

            float bx1, by1, bx2, by2;
            if (c == 0.0f) { bx1 = ax1[i]; by1 = ay1[i]; bx2 = ax2[i]; by2 = ay2[i]; }
            else           { bx1 = gb.x;   by1 = gb.y;   bx2 = gb.z;   by2 = gb.w;   }

            const float tcx = 0.5f * (bx1 + bx2), tcy = 0.5f * (by1 + by2);
            const float tw  = bx2 - bx1,          th  = by2 - by1;
            const float acx = 0.5f * (ax1[i] + ax2[i]), acy = 0.5f * (ay1[i] + ay2[i]);
            const float aw  = ax2[i] - ax1[i],          ah  = ay2[i] - ay1[i];

            outbuf[i * 5 + 0] = fast_div(tcx - acx, aw);
            outbuf[i * 5 + 1] = fast_div(tcy - acy, ah);
            outbuf[i * 5 + 2] = __logf(fast_div(tw, aw));
            outbuf[i * 5 + 3] = __logf(fast_div(th, ah));
            outbuf[i * 5 + 4] = pos ? c : 0.0f;
        }
        // 20 contiguous, 16B-aligned floats -> 5x STG.128 (all 4 anchors valid:
        // NANCH % 4 == 0 and threads are APT-aligned)
        float4* lb = reinterpret_cast<float4*>(out_labeled + ((size_t)b * NANCH + n0) * 5);
#pragma unroll
        for (int i = 0; i < 5; i++)
            lb[i] = *reinterpret_cast<const float4*>(&outbuf[i * 4]);
    }

    // drain outstanding bulk copies before block teardown
    if (tid == 0) bulk_wait<0>();
}

extern "C" void kernel_launch(void* const* d_in, const int* in_sizes, int n_in,
                              void* d_out, int out_size)
{
    const float* labels = (const float*)d_in[0];   // [64,100,5]
    const float* dboxes = (const float*)d_in[1];   // [8732,4]

    float* out_labeled = (float*)d_out;                                   // [64,8732,5]
    float* out_ious    = (float*)d_out + (size_t)BATCH * NANCH * 5;       // [64,101,8732]

    dim3 grid(NBLKX, BATCH);                                              // (18, 64)
    encode_layer_kernel<<<grid, TPB>>>(labels, dboxes, out_labeled, out_ious);
}

// round 9
// speedup vs baseline: 1.0826x; 1.0826x over previous
#include <cuda_runtime.h>

// EncodeLayer: SSD anchor matching + box encoding.
// labels:        [B=64, M=100, 5]  (x1,y1,x2,y2,cls), cls==0 => padding row
// default_boxes: [N=8732, 4]
// out: labeled [B, N, 5] (2,794,240 f32) then ious [B, 101, N] (56,443,648 f32)

#define BATCH   64
#define MROWS   100
#define NGT     101          // MROWS + prepended zero row
#define NANCH   8732
#define TPB     128
#define APT     4            // anchors per thread (8732 % 4 == 0)
#define ANCH_PER_BLOCK (TPB * APT)   // 512

// Hot-loop division: rcp.approx (~1-2 ulp) + FMUL. Exact for n==0.
__device__ __forceinline__ float approx_div(float n, float d) {
    float r;
    asm("rcp.approx.f32 %0, %1;" : "=f"(r) : "f"(d));
    return n * r;
}

// Epilogue division: one quotient refinement on top (~0.5-1 ulp), branch-free.
__device__ __forceinline__ float fast_div(float n, float d) {
    float r;
    asm("rcp.approx.f32 %0, %1;" : "=f"(r) : "f"(d));
    float q0  = n * r;
    float rem = __fmaf_rn(-d, q0, n);
    return __fmaf_rn(rem, r, q0);
}

__global__ __launch_bounds__(TPB)
void encode_layer_kernel(const float* __restrict__ labels,
                         const float* __restrict__ dboxes,
                         float* __restrict__ out_labeled,   // [B, N, 5]
                         float* __restrict__ out_ious)      // [B, 101, N]
{
    __shared__ float4 sbox[NGT];   // gt box (zeroed if cls==0, row 0 = zero row)
    __shared__ float  sarea[NGT];  // gt area (0 for invalid rows)
    __shared__ float  scls[NGT];   // original class value

    const int b   = blockIdx.y;
    const int tid = threadIdx.x;

    // ---- stage GT table for this batch into smem ----
    for (int r = tid; r < NGT; r += TPB) {
        float x1 = 0.f, y1 = 0.f, x2 = 0.f, y2 = 0.f, c = 0.f;
        if (r > 0) {
            const float* L = labels + ((size_t)b * MROWS + (r - 1)) * 5;
            x1 = L[0]; y1 = L[1]; x2 = L[2]; y2 = L[3]; c = L[4];
            if (c == 0.0f) { x1 = 0.f; y1 = 0.f; x2 = 0.f; y2 = 0.f; }
        }
        sbox[r]  = make_float4(x1, y1, x2, y2);
        sarea[r] = (x2 - x1) * (y2 - y1);
        scls[r]  = c;
    }
    __syncthreads();

    const int n0 = (blockIdx.x * TPB + tid) * APT;
    if (n0 >= NANCH) return;   // 8732 % 4 == 0, so n0..n0+3 all valid

    // ---- per-thread anchor registers ----
    float ax1[APT], ay1[APT], ax2[APT], ay2[APT], aarea[APT];
#pragma unroll
    for (int i = 0; i < APT; i++) {
        const float4 db = *reinterpret_cast<const float4*>(dboxes + (size_t)(n0 + i) * 4);
        ax1[i] = db.x; ay1[i] = db.y; ax2[i] = db.z; ay2[i] = db.w;
        aarea[i] = (db.z - db.x) * (db.w - db.y);
    }

    // argmax state: row 0 (zero row, iou==0) is the default winner; strict >
    // against best=0 reproduces jnp.argmax first-occurrence semantics.
    float best[APT] = {0.f, 0.f, 0.f, 0.f};
    int   bidx[APT] = {0, 0, 0, 0};

    float* iou_ptr = out_ious + (size_t)b * NGT * NANCH + n0;

    // ---- peel m=0: prepended zero row -> iou row is all zeros, no math ----
    *reinterpret_cast<float4*>(iou_ptr) = make_float4(0.f, 0.f, 0.f, 0.f);
    iou_ptr += NANCH;

    // ---- main loop: 100 real GT rows, outer x25 / inner x4 so the row
    //      stride (mm*NANCH) folds into STG immediate offsets; the 64-bit
    //      pointer add happens once per 4 rows.
    for (int mo = 0; mo < MROWS; mo += 4) {
#pragma unroll
        for (int mm = 0; mm < 4; mm++) {
            const int m = 1 + mo + mm;
            const float4 tb = sbox[m];
            const float  ta = sarea[m];
            float4 o;
            float* op = &o.x;
#pragma unroll
            for (int i = 0; i < APT; i++) {
                float ix1 = fmaxf(tb.x, ax1[i]);
                float iy1 = fmaxf(tb.y, ay1[i]);
                float ix2 = fminf(tb.z, ax2[i]);
                float iy2 = fminf(tb.w, ay2[i]);
                // w,h < 1 always (box widths <= ~0.4), so saturate == max(.,0);
                // ptxas fuses this into FADD.SAT.
                float w = __saturatef(ix2 - ix1);
                float h = __saturatef(iy2 - iy1);
                float inter = w * h;
                float denom = (ta + aarea[i]) - inter;
                float iou = approx_div(inter, denom);
                op[i] = iou;
                // pred-as-DATA argmax: FSETP -> SEL (4cyc) + FMNMX (4cyc);
                // avoids the 13-cyc @P-guard latency on the loop-carried best[].
                // Order matters: bidx uses the OLD best (strict >, first occurrence).
                bidx[i] = (iou > best[i]) ? m : bidx[i];
                best[i] = fmaxf(best[i], iou);
            }
            *reinterpret_cast<float4*>(iou_ptr + (size_t)mm * NANCH) = o;
        }
        iou_ptr += 4 * NANCH;
    }

    // ---- epilogue: gather winner, encode offsets ----
    float outbuf[APT * 5];
#pragma unroll
    for (int i = 0; i < APT; i++) {
        const bool pos = best[i] > 0.5f;
        const int  idx = pos ? bidx[i] : 0;
        const float4 gb = sbox[idx];
        const float  c  = scls[idx];

        float bx1, by1, bx2, by2;
        if (c == 0.0f) { bx1 = ax1[i]; by1 = ay1[i]; bx2 = ax2[i]; by2 = ay2[i]; }
        else           { bx1 = gb.x;   by1 = gb.y;   bx2 = gb.z;   by2 = gb.w;   }

        const float tcx = 0.5f * (bx1 + bx2), tcy = 0.5f * (by1 + by2);
        const float tw  = bx2 - bx1,          th  = by2 - by1;
        const float acx = 0.5f * (ax1[i] + ax2[i]), acy = 0.5f * (ay1[i] + ay2[i]);
        const float aw  = ax2[i] - ax1[i],          ah  = ay2[i] - ay1[i];

        outbuf[i * 5 + 0] = fast_div(tcx - acx, aw);
        outbuf[i * 5 + 1] = fast_div(tcy - acy, ah);
        outbuf[i * 5 + 2] = __logf(fast_div(tw, aw));
        outbuf[i * 5 + 3] = __logf(fast_div(th, ah));
        outbuf[i * 5 + 4] = pos ? c : 0.0f;
    }

    // 20 contiguous, 16B-aligned floats -> 5x STG.128
    float4* lb = reinterpret_cast<float4*>(out_labeled + ((size_t)b * NANCH + n0) * 5);
#pragma unroll
    for (int i = 0; i < 5; i++)
        lb[i] = *reinterpret_cast<const float4*>(&outbuf[i * 4]);
}

extern "C" void kernel_launch(void* const* d_in, const int* in_sizes, int n_in,
                              void* d_out, int out_size)
{
    const float* labels = (const float*)d_in[0];   // [64,100,5]
    const float* dboxes = (const float*)d_in[1];   // [8732,4]

    float* out_labeled = (float*)d_out;                                   // [64,8732,5]
    float* out_ious    = (float*)d_out + (size_t)BATCH * NANCH * 5;       // [64,101,8732]

    dim3 grid((NANCH + ANCH_PER_BLOCK - 1) / ANCH_PER_BLOCK, BATCH);      // (18, 64)
    encode_layer_kernel<<<grid, TPB>>>(labels, dboxes, out_labeled, out_ious);
}

// round 10
// speedup vs baseline: 1.1133x; 1.0283x over previous
#include <cuda_runtime.h>

// EncodeLayer: SSD anchor matching + box encoding.
// labels:        [B=64, M=100, 5]  (x1,y1,x2,y2,cls), cls==0 => padding row
// default_boxes: [N=8732, 4]
// out: labeled [B, N, 5] (2,794,240 f32) then ious [B, 101, N] (56,443,648 f32)

#define BATCH   64
#define MROWS   100
#define NGT     101          // MROWS + prepended zero row
#define NANCH   8732
#define TPB     128
#define APT     4            // anchors per thread (8732 % 4 == 0)
#define ANCH_PER_BLOCK (TPB * APT)   // 512
#define MUNROLL 10           // 100 rows = 10 groups of 10

// Hot-loop division: rcp.approx (~1-2 ulp) + FMUL. Exact for n==0.
__device__ __forceinline__ float approx_div(float n, float d) {
    float r;
    asm("rcp.approx.f32 %0, %1;" : "=f"(r) : "f"(d));
    return n * r;
}

// Epilogue division: one quotient refinement on top (~0.5-1 ulp), branch-free.
__device__ __forceinline__ float fast_div(float n, float d) {
    float r;
    asm("rcp.approx.f32 %0, %1;" : "=f"(r) : "f"(d));
    float q0  = n * r;
    float rem = __fmaf_rn(-d, q0, n);
    return __fmaf_rn(rem, r, q0);
}

__global__ __launch_bounds__(TPB)
void encode_layer_kernel(const float* __restrict__ labels,
                         const float* __restrict__ dboxes,
                         float* __restrict__ out_labeled,   // [B, N, 5]
                         float* __restrict__ out_ious)      // [B, 101, N]
{
    __shared__ float4 sbox[NGT];   // gt box (zeroed if cls==0, row 0 = zero row)
    __shared__ float  sarea[NGT];  // gt area (0 for invalid rows)
    __shared__ float  scls[NGT];   // original class value

    const int b   = blockIdx.y;
    const int tid = threadIdx.x;

    // ---- stage GT table for this batch into smem ----
    for (int r = tid; r < NGT; r += TPB) {
        float x1 = 0.f, y1 = 0.f, x2 = 0.f, y2 = 0.f, c = 0.f;
        if (r > 0) {
            const float* L = labels + ((size_t)b * MROWS + (r - 1)) * 5;
            x1 = L[0]; y1 = L[1]; x2 = L[2]; y2 = L[3]; c = L[4];
            if (c == 0.0f) { x1 = 0.f; y1 = 0.f; x2 = 0.f; y2 = 0.f; }
        }
        sbox[r]  = make_float4(x1, y1, x2, y2);
        sarea[r] = (x2 - x1) * (y2 - y1);
        scls[r]  = c;
    }
    __syncthreads();

    const int n0 = (blockIdx.x * TPB + tid) * APT;
    if (n0 >= NANCH) return;   // 8732 % 4 == 0, so n0..n0+3 all valid

    // ---- per-thread anchor registers ----
    float ax1[APT], ay1[APT], ax2[APT], ay2[APT], aarea[APT];
#pragma unroll
    for (int i = 0; i < APT; i++) {
        const float4 db = *reinterpret_cast<const float4*>(dboxes + (size_t)(n0 + i) * 4);
        ax1[i] = db.x; ay1[i] = db.y; ax2[i] = db.z; ay2[i] = db.w;
        aarea[i] = (db.z - db.x) * (db.w - db.y);
    }

    // argmax state: row 0 (zero row, iou==0) is the default winner; strict >
    // against best=0 reproduces jnp.argmax first-occurrence semantics.
    float best[APT] = {0.f, 0.f, 0.f, 0.f};
    int   bidx[APT] = {0, 0, 0, 0};

    float* iou_ptr = out_ious + (size_t)b * NGT * NANCH + n0;

    // ---- peel m=0: prepended zero row -> iou row is all zeros, no math ----
    __stcs(reinterpret_cast<float4*>(iou_ptr), make_float4(0.f, 0.f, 0.f, 0.f));
    iou_ptr += NANCH;

    // ---- main loop: 100 real GT rows, 10 groups of 10. Row stride folds
    //      into STG immediate offsets; 40 independent IoU chains per group
    //      give the scheduler a wide ILP window.
    for (int mo = 0; mo < MROWS; mo += MUNROLL) {
#pragma unroll
        for (int mm = 0; mm < MUNROLL; mm++) {
            const int m = 1 + mo + mm;
            const float4 tb = sbox[m];
            const float  ta = sarea[m];
            float4 o;
            float* op = &o.x;
#pragma unroll
            for (int i = 0; i < APT; i++) {
                float ix1 = fmaxf(tb.x, ax1[i]);
                float iy1 = fmaxf(tb.y, ay1[i]);
                float ix2 = fminf(tb.z, ax2[i]);
                float iy2 = fminf(tb.w, ay2[i]);
                // w,h < 1 always (box widths <= ~0.4), so saturate == max(.,0);
                // ptxas fuses this into FADD.SAT.
                float w = __saturatef(ix2 - ix1);
                float h = __saturatef(iy2 - iy1);
                float inter = w * h;
                float denom = (ta + aarea[i]) - inter;
                float iou = approx_div(inter, denom);
                op[i] = iou;
                if (iou > best[i]) { best[i] = iou; bidx[i] = m; }  // first-occurrence argmax
            }
            __stcs(reinterpret_cast<float4*>(iou_ptr + (size_t)mm * NANCH), o);
        }
        iou_ptr += (size_t)MUNROLL * NANCH;
    }

    // ---- epilogue: gather winner, encode offsets ----
    float outbuf[APT * 5];
#pragma unroll
    for (int i = 0; i < APT; i++) {
        const bool pos = best[i] > 0.5f;
        const int  idx = pos ? bidx[i] : 0;
        const float4 gb = sbox[idx];
        const float  c  = scls[idx];

        float bx1, by1, bx2, by2;
        if (c == 0.0f) { bx1 = ax1[i]; by1 = ay1[i]; bx2 = ax2[i]; by2 = ay2[i]; }
        else           { bx1 = gb.x;   by1 = gb.y;   bx2 = gb.z;   by2 = gb.w;   }

        const float tcx = 0.5f * (bx1 + bx2), tcy = 0.5f * (by1 + by2);
        const float tw  = bx2 - bx1,          th  = by2 - by1;
        const float acx = 0.5f * (ax1[i] + ax2[i]), acy = 0.5f * (ay1[i] + ay2[i]);
        const float aw  = ax2[i] - ax1[i],          ah  = ay2[i] - ay1[i];

        outbuf[i * 5 + 0] = fast_div(tcx - acx, aw);
        outbuf[i * 5 + 1] = fast_div(tcy - acy, ah);
        outbuf[i * 5 + 2] = __logf(fast_div(tw, aw));
        outbuf[i * 5 + 3] = __logf(fast_div(th, ah));
        outbuf[i * 5 + 4] = pos ? c : 0.0f;
    }

    // 20 contiguous, 16B-aligned floats -> 5x STG.128 (streaming)
    float4* lb = reinterpret_cast<float4*>(out_labeled + ((size_t)b * NANCH + n0) * 5);
#pragma unroll
    for (int i = 0; i < 5; i++)
        __stcs(lb + i, *reinterpret_cast<const float4*>(&outbuf[i * 4]));
}

extern "C" void kernel_launch(void* const* d_in, const int* in_sizes, int n_in,
                              void* d_out, int out_size)
{
    const float* labels = (const float*)d_in[0];   // [64,100,5]
    const float* dboxes = (const float*)d_in[1];   // [8732,4]

    float* out_labeled = (float*)d_out;                                   // [64,8732,5]
    float* out_ious    = (float*)d_out + (size_t)BATCH * NANCH * 5;       // [64,101,8732]

    dim3 grid((NANCH + ANCH_PER_BLOCK - 1) / ANCH_PER_BLOCK, BATCH);      // (18, 64)
    encode_layer_kernel<<<grid, TPB>>>(labels, dboxes, out_labeled, out_ious);
}